// round 14
// baseline (speedup 1.0000x reference)
#include <cuda_runtime.h>
#include <cstdint>
#include <math.h>

// Problem constants (fixed by the dataset)
#define VG   20000
#define BGR  8
#define KEIG 128
#define DCH  128

#define NCHUNK   37      // 37 chunks x 8 graphs = 296 CTAs = one 2-CTA/SM wave
#define TB_CHUNK 552     // 37 * 552 = 20424 >= 20000
#define TB_ROWS  24      // v-rows per stage
#define TB_NS    23      // stages per chunk (23*24 = 552)
#define TB_P     136     // pitch: conflict-free frag reads + row staging
#define TB_BUFELEMS (2 * TB_ROWS * TB_P)   // sE+sX per stage (uint32 elems)

#define FB_KC    16      // k per chunk in from_basis
#define FB_NCK   8       // k chunks
#define FB_P     20      // pitch: conflict-free frag reads (20g+t distinct mod 32)
#define FB_BUFELEMS (2 * 128 * FB_P)

// Scratch (device globals — no allocations)
__device__ float g_part[BGR * NCHUNK * KEIG * DCH];  // per-chunk partial x_spec
__device__ float g_shat_T[BGR * DCH * KEIG];         // scaled spectrum, tf32 bits, [b][d][k]

// ---------------------------------------------------------------------------
// helpers
// ---------------------------------------------------------------------------
__device__ __forceinline__ uint32_t f2tf32(float x) {
    uint32_t r;
    asm("cvt.rna.tf32.f32 %0, %1;" : "=r"(r) : "f"(x));
    return r;
}
__device__ __forceinline__ uint32_t smem_u32(const void* p) {
    uint32_t a;
    asm("{ .reg .u64 t; cvta.to.shared.u64 t, %1; cvt.u32.u64 %0, t; }"
        : "=r"(a) : "l"(p));
    return a;
}
// 16B async copy; zero-fill (sz=0) when pred==false (src must stay valid)
__device__ __forceinline__ void cpa16(uint32_t dst, const void* src, bool pred) {
    int sz = pred ? 16 : 0;
    asm volatile("cp.async.cg.shared.global [%0], [%1], 16, %2;"
                 :: "r"(dst), "l"(src), "r"(sz));
}
#define CP_COMMIT() asm volatile("cp.async.commit_group;" ::: "memory")
#define CP_WAIT2()  asm volatile("cp.async.wait_group 2;" ::: "memory")

__device__ __forceinline__ void mma8(float c[4], const uint32_t a[4],
                                     const uint32_t b[2]) {
    asm volatile(
        "mma.sync.aligned.m16n8k8.row.col.f32.tf32.tf32.f32 "
        "{%0,%1,%2,%3}, {%4,%5,%6,%7}, {%8,%9}, {%0,%1,%2,%3};"
        : "+f"(c[0]), "+f"(c[1]), "+f"(c[2]), "+f"(c[3])
        : "r"(a[0]), "r"(a[1]), "r"(a[2]), "r"(a[3]),
          "r"(b[0]), "r"(b[1]));
}

// ---------------------------------------------------------------------------
// Kernel A (to_basis): g_part[b,chunk,k,d] = sum_{v} E[v,k] * (m[v]*X[v,d])
// 4 buffers x 24-row stages, depth-3 cp.async, SINGLE barrier per stage:
//   wait -> sync -> issue(s+3 into freed buf) -> commit -> mma(buf s)
// ---------------------------------------------------------------------------
__device__ __forceinline__ void tb_issue(int sv, uint32_t uE, uint32_t uX,
                                         uint32_t uM,
                                         const float* Eb, const float* Xb,
                                         const float* Mb, int tid) {
#pragma unroll
    for (int r = 0; r < 3; r++) {
        int idx = r * 256 + tid;          // 0..767
        int row = idx >> 5;               // 0..23
        int c4  = idx & 31;               // 0..31
        int gv  = sv + row;
        bool p  = gv < VG;
        const float* es = p ? (Eb + (size_t)gv * KEIG + c4 * 4) : Eb;
        const float* xs = p ? (Xb + (size_t)gv * DCH  + c4 * 4) : Xb;
        uint32_t off = (uint32_t)(row * TB_P + c4 * 4) * 4u;
        cpa16(uE + off, es, p);
        cpa16(uX + off, xs, p);
    }
    if (tid < 6) {
        int o = tid * 4;                  // 0..20 (covers 24 rows)
        bool p = (sv + o) < VG;           // sv+o ≡ 0 mod 4, VG ≡ 0 mod 4 -> safe
        const float* ms = p ? (Mb + sv + o) : Mb;
        cpa16(uM + o * 4u, ms, p);
    }
}

__global__ __launch_bounds__(256, 2)
void gemm_tobasis_tc(const float* __restrict__ x,
                     const float* __restrict__ mass,
                     const float* __restrict__ evecs) {
    extern __shared__ uint32_t sm[];
    float* sMall = (float*)(sm + 4 * TB_BUFELEMS);       // [4][24]
    const uint32_t uBase = smem_u32(sm);
    const uint32_t uMbase = smem_u32(sMall);

    const int b     = blockIdx.y;
    const int cbase = blockIdx.x * TB_CHUNK;
    const int tid   = threadIdx.x;
    const int lane  = tid & 31;
    const int wid   = tid >> 5;
    const int m0    = (wid & 1) * 64;   // k-eig offset
    const int n0    = (wid >> 1) * 32;  // d offset
    const int g     = lane >> 2;
    const int t     = lane & 3;

    const float* Eb = evecs + (size_t)b * VG * KEIG;
    const float* Xb = x     + (size_t)b * VG * DCH;
    const float* Mb = mass  + (size_t)b * VG;

    float c[4][4][4];
#pragma unroll
    for (int mi = 0; mi < 4; mi++)
#pragma unroll
        for (int ni = 0; ni < 4; ni++)
#pragma unroll
            for (int q = 0; q < 4; q++) c[mi][ni][q] = 0.f;

    // prologue: 3 groups in flight
#pragma unroll
    for (int s = 0; s < 3; s++) {
        tb_issue(cbase + s * TB_ROWS,
                 uBase + (uint32_t)(s * TB_BUFELEMS) * 4u,
                 uBase + (uint32_t)(s * TB_BUFELEMS + TB_ROWS * TB_P) * 4u,
                 uMbase + (uint32_t)(s * TB_ROWS) * 4u,
                 Eb, Xb, Mb, tid);
        CP_COMMIT();
    }

    for (int s = 0; s < TB_NS; s++) {
        const int bi = s & 3;
        const int bn = (s + 3) & 3;
        CP_WAIT2();
        __syncthreads();   // group s visible; buf bn (read at s-1) now free

        // issue next stage's loads FIRST so they overlap this stage's mma
        if (s + 3 < TB_NS) {
            tb_issue(cbase + (s + 3) * TB_ROWS,
                     uBase + (uint32_t)(bn * TB_BUFELEMS) * 4u,
                     uBase + (uint32_t)(bn * TB_BUFELEMS + TB_ROWS * TB_P) * 4u,
                     uMbase + (uint32_t)(bn * TB_ROWS) * 4u,
                     Eb, Xb, Mb, tid);
        }
        CP_COMMIT();       // unconditional: keeps wait_group accounting exact

        const uint32_t* sE = sm + bi * TB_BUFELEMS;
        const uint32_t* sX = sE + TB_ROWS * TB_P;
        const float* sMs = sMall + bi * TB_ROWS;

#pragma unroll
        for (int kv = 0; kv < TB_ROWS; kv += 8) {
            const uint32_t* eLo = sE + (kv + t) * TB_P;
            const uint32_t* eHi = sE + (kv + t + 4) * TB_P;
            const uint32_t* xLo = sX + (kv + t) * TB_P;
            const uint32_t* xHi = sX + (kv + t + 4) * TB_P;
            float mLo = sMs[kv + t];
            float mHi = sMs[kv + t + 4];
            uint32_t af[4][4], bf[4][2];
#pragma unroll
            for (int mi = 0; mi < 4; mi++) {
                int mIdx = m0 + mi * 16 + g;
                af[mi][0] = f2tf32(__uint_as_float(eLo[mIdx]));
                af[mi][1] = f2tf32(__uint_as_float(eLo[mIdx + 8]));
                af[mi][2] = f2tf32(__uint_as_float(eHi[mIdx]));
                af[mi][3] = f2tf32(__uint_as_float(eHi[mIdx + 8]));
            }
#pragma unroll
            for (int ni = 0; ni < 4; ni++) {
                int nIdx = n0 + ni * 8 + g;
                bf[ni][0] = f2tf32(__uint_as_float(xLo[nIdx]) * mLo);
                bf[ni][1] = f2tf32(__uint_as_float(xHi[nIdx]) * mHi);
            }
#pragma unroll
            for (int mi = 0; mi < 4; mi++)
#pragma unroll
                for (int ni = 0; ni < 4; ni++) mma8(c[mi][ni], af[mi], bf[ni]);
        }
        // NO trailing barrier — next stage's entry barrier protects reuse
    }

    // epilogue: private partial slab, plain stores
    float* dst = g_part + ((size_t)(b * NCHUNK + blockIdx.x) << 14);
#pragma unroll
    for (int mi = 0; mi < 4; mi++) {
        int r0 = m0 + mi * 16 + g;
#pragma unroll
        for (int ni = 0; ni < 4; ni++) {
            int col = n0 + ni * 8 + 2 * t;
            *(float2*)&dst[r0 * DCH + col] =
                make_float2(c[mi][ni][0], c[mi][ni][1]);
            *(float2*)&dst[(r0 + 8) * DCH + col] =
                make_float2(c[mi][ni][2], c[mi][ni][3]);
        }
    }
}

// ---------------------------------------------------------------------------
// Kernel B: reduce NCHUNK partials + exp scale; store TF32 BITS transposed
// ---------------------------------------------------------------------------
__global__ void spectral_reduce_scale(const float* __restrict__ evals,
                                      const float* __restrict__ tdiff) {
    int i = blockIdx.x * 256 + threadIdx.x;   // over b*K*D
    if (i >= BGR * KEIG * DCH) return;
    int d = i & 127;
    int k = (i >> 7) & 127;
    int b = i >> 14;
    const float* p = g_part + ((size_t)(b * NCHUNK) << 14) + k * DCH + d;
    float s = 0.f;
#pragma unroll
    for (int ch = 0; ch < NCHUNK; ch++) s += p[(size_t)ch << 14];
    float tt = fmaxf(tdiff[d], 1e-8f);
    float val = s * expf(-evals[b * KEIG + k] * tt);
    g_shat_T[(b << 14) + (d << 7) + k] = __uint_as_float(f2tf32(val));
}

// ---------------------------------------------------------------------------
// Kernel C (from_basis): out[v,d] = sum_k E[v,k] * S_T[d,k]
// 8 k-chunks of 16, 4 buffers, depth-3, single barrier per stage.
// S pre-rounded tf32 (no cvt); E cvt at frag read.
// ---------------------------------------------------------------------------
__device__ __forceinline__ void fb_issue(int k0, uint32_t uE, uint32_t uS,
                                         const float* Eb, const float* Sb,
                                         int v0, int tid) {
#pragma unroll
    for (int r = 0; r < 2; r++) {
        int idx = r * 256 + tid;          // 0..511
        int row = idx & 127;              // warp-contiguous rows -> CF STS.128
        int c4  = idx >> 7;               // 0..3
        uint32_t off = (uint32_t)(row * FB_P + c4 * 4) * 4u;
        cpa16(uS + off, Sb + (size_t)row * KEIG + k0 + c4 * 4, true);
        int v = v0 + row;
        bool p = v < VG;
        const float* es = p ? (Eb + (size_t)v * KEIG + k0 + c4 * 4) : Eb;
        cpa16(uE + off, es, p);
    }
}

__global__ __launch_bounds__(256, 2)
void gemm_frombasis_tc(const float* __restrict__ evecs,
                       float* __restrict__ out) {
    extern __shared__ uint32_t sm[];
    const uint32_t uBase = smem_u32(sm);

    const int b    = blockIdx.y;
    const int v0   = blockIdx.x * 128;
    const int tid  = threadIdx.x;
    const int lane = tid & 31;
    const int wid  = tid >> 5;
    const int m0   = (wid & 1) * 64;    // v offset
    const int n0   = (wid >> 1) * 32;   // d offset
    const int g    = lane >> 2;
    const int t    = lane & 3;

    const float* Eb = evecs    + (size_t)b * VG * KEIG;
    const float* Sb = g_shat_T + ((size_t)b << 14);

    float c[4][4][4];
#pragma unroll
    for (int mi = 0; mi < 4; mi++)
#pragma unroll
        for (int ni = 0; ni < 4; ni++)
#pragma unroll
            for (int q = 0; q < 4; q++) c[mi][ni][q] = 0.f;

    // prologue: 3 groups in flight
#pragma unroll
    for (int s = 0; s < 3; s++) {
        fb_issue(s * FB_KC,
                 uBase + (uint32_t)(s * FB_BUFELEMS) * 4u,
                 uBase + (uint32_t)(s * FB_BUFELEMS + 128 * FB_P) * 4u,
                 Eb, Sb, v0, tid);
        CP_COMMIT();
    }

#pragma unroll
    for (int ck = 0; ck < FB_NCK; ck++) {
        const int bi = ck & 3;
        const int bn = (ck + 3) & 3;
        CP_WAIT2();
        __syncthreads();

        if (ck + 3 < FB_NCK) {
            fb_issue((ck + 3) * FB_KC,
                     uBase + (uint32_t)(bn * FB_BUFELEMS) * 4u,
                     uBase + (uint32_t)(bn * FB_BUFELEMS + 128 * FB_P) * 4u,
                     Eb, Sb, v0, tid);
        }
        CP_COMMIT();

        const uint32_t* sE = sm + bi * FB_BUFELEMS;
        const uint32_t* sS = sE + 128 * FB_P;

#pragma unroll
        for (int ks = 0; ks < FB_KC; ks += 8) {
            uint32_t af[4][4], bf[4][2];
#pragma unroll
            for (int mi = 0; mi < 4; mi++) {
                const uint32_t* p = sE + (m0 + mi * 16 + g) * FB_P + ks + t;
                af[mi][0] = f2tf32(__uint_as_float(p[0]));
                af[mi][1] = f2tf32(__uint_as_float(p[8 * FB_P]));
                af[mi][2] = f2tf32(__uint_as_float(p[4]));
                af[mi][3] = f2tf32(__uint_as_float(p[8 * FB_P + 4]));
            }
#pragma unroll
            for (int ni = 0; ni < 4; ni++) {
                const uint32_t* p = sS + (n0 + ni * 8 + g) * FB_P + ks + t;
                bf[ni][0] = p[0];
                bf[ni][1] = p[4];
            }
#pragma unroll
            for (int mi = 0; mi < 4; mi++)
#pragma unroll
                for (int ni = 0; ni < 4; ni++) mma8(c[mi][ni], af[mi], bf[ni]);
        }
    }

    // epilogue: direct, sector-aligned float2 stores
#pragma unroll
    for (int mi = 0; mi < 4; mi++) {
        int vlo = v0 + m0 + mi * 16 + g;
#pragma unroll
        for (int ni = 0; ni < 4; ni++) {
            int col = n0 + ni * 8 + 2 * t;
            if (vlo < VG)
                *(float2*)(out + (size_t)(b * VG + vlo) * DCH + col) =
                    make_float2(c[mi][ni][0], c[mi][ni][1]);
            if (vlo + 8 < VG)
                *(float2*)(out + (size_t)(b * VG + vlo + 8) * DCH + col) =
                    make_float2(c[mi][ni][2], c[mi][ni][3]);
        }
    }
}

// ---------------------------------------------------------------------------
// Launch
// Inputs: 0:x (V,D) f32, 1:mass (V,) f32, 2:evals (B*K,) f32,
// 3:evecs (V,K) f32, 4:diffusion_time (D,) f32, 5:batch (V,) i32, 6:bs
// Output: (V,D) f32
// ---------------------------------------------------------------------------
extern "C" void kernel_launch(void* const* d_in, const int* in_sizes, int n_in,
                              void* d_out, int out_size) {
    const float* x     = (const float*)d_in[0];
    const float* mass  = (const float*)d_in[1];
    const float* evals = (const float*)d_in[2];
    const float* evecs = (const float*)d_in[3];
    const float* tdiff = (const float*)d_in[4];
    float* out = (float*)d_out;

    (void)in_sizes; (void)n_in; (void)out_size;

    const int TB_SMEM = (4 * TB_BUFELEMS + 4 * TB_ROWS) * 4;  // 104832 B
    const int FB_SMEM = (4 * FB_BUFELEMS) * 4;                // 81920 B
    cudaFuncSetAttribute(gemm_tobasis_tc,
                         cudaFuncAttributeMaxDynamicSharedMemorySize, TB_SMEM);
    cudaFuncSetAttribute(gemm_frombasis_tc,
                         cudaFuncAttributeMaxDynamicSharedMemorySize, FB_SMEM);

    dim3 gridA(NCHUNK, BGR);
    gemm_tobasis_tc<<<gridA, 256, TB_SMEM>>>(x, mass, evecs);

    spectral_reduce_scale<<<(BGR * KEIG * DCH + 255) / 256, 256>>>(evals, tdiff);

    dim3 gridC((VG + 127) / 128, BGR);
    gemm_frombasis_tc<<<gridC, 256, FB_SMEM>>>(evecs, out);
}

// round 15
// speedup vs baseline: 1.2792x; 1.2792x over previous
#include <cuda_runtime.h>
#include <cstdint>
#include <math.h>

// Problem constants (fixed by the dataset)
#define VG   20000
#define BGR  8
#define KEIG 128
#define DCH  128

#define NCHUNK   37      // 37 chunks x 8 graphs = 296 CTAs = one 2-CTA/SM wave
#define TB_CHUNK 544     // 37 * 544 = 20128 >= 20000
#define TB_ROWS  32      // v-rows per stage
#define TB_NS    17      // stages per chunk
#define TB_P     136     // pitch: conflict-free frag reads + row staging
#define TB_BUFELEMS (2 * TB_ROWS * TB_P)   // sE+sX per stage (uint32 elems)

#define FB_KC    32      // k per chunk in from_basis
#define FB_NCK   4       // k chunks
#define FB_P     36      // pitch: conflict-free frag reads + row staging
#define FB_BUFELEMS (2 * 128 * FB_P)

// Scratch (device globals — no allocations)
__device__ float g_part[BGR * NCHUNK * KEIG * DCH];  // per-chunk partial x_spec
__device__ float g_shat_T[BGR * DCH * KEIG];         // scaled spectrum, tf32 bits, [b][d][k]

// ---------------------------------------------------------------------------
// helpers
// ---------------------------------------------------------------------------
__device__ __forceinline__ uint32_t f2tf32(float x) {
    uint32_t r;
    asm("cvt.rna.tf32.f32 %0, %1;" : "=r"(r) : "f"(x));
    return r;
}
__device__ __forceinline__ uint32_t smem_u32(const void* p) {
    uint32_t a;
    asm("{ .reg .u64 t; cvta.to.shared.u64 t, %1; cvt.u32.u64 %0, t; }"
        : "=r"(a) : "l"(p));
    return a;
}
// 16B async copy; zero-fill (sz=0) when pred==false (src must stay valid)
__device__ __forceinline__ void cpa16(uint32_t dst, const void* src, bool pred) {
    int sz = pred ? 16 : 0;
    asm volatile("cp.async.cg.shared.global [%0], [%1], 16, %2;"
                 :: "r"(dst), "l"(src), "r"(sz));
}
#define CP_COMMIT() asm volatile("cp.async.commit_group;" ::: "memory")
#define CP_WAIT2()  asm volatile("cp.async.wait_group 2;" ::: "memory")

__device__ __forceinline__ void mma8(float c[4], const uint32_t a[4],
                                     const uint32_t b[2]) {
    asm volatile(
        "mma.sync.aligned.m16n8k8.row.col.f32.tf32.tf32.f32 "
        "{%0,%1,%2,%3}, {%4,%5,%6,%7}, {%8,%9}, {%0,%1,%2,%3};"
        : "+f"(c[0]), "+f"(c[1]), "+f"(c[2]), "+f"(c[3])
        : "r"(a[0]), "r"(a[1]), "r"(a[2]), "r"(a[3]),
          "r"(b[0]), "r"(b[1]));
}

// ---------------------------------------------------------------------------
// Kernel A (to_basis): g_part[b,chunk,k,d] = sum_{v} E[v,k] * (m[v]*X[v,d])
// 128 threads = 4 warps in 2x2, warp tile 64(k) x 64(d), 128 acc/thread.
// 3-stage cp.async pipeline identical to R10.
// ---------------------------------------------------------------------------
__device__ __forceinline__ void tb_issue(int sv, uint32_t uE, uint32_t uX,
                                         uint32_t uM,
                                         const float* Eb, const float* Xb,
                                         const float* Mb, int tid) {
#pragma unroll
    for (int r = 0; r < 8; r++) {
        int idx = r * 128 + tid;          // 0..1023
        int row = idx >> 5;               // 0..31
        int c4  = idx & 31;               // 0..31
        int gv  = sv + row;
        bool p  = gv < VG;
        const float* es = p ? (Eb + (size_t)gv * KEIG + c4 * 4) : Eb;
        const float* xs = p ? (Xb + (size_t)gv * DCH  + c4 * 4) : Xb;
        uint32_t off = (uint32_t)(row * TB_P + c4 * 4) * 4u;
        cpa16(uE + off, es, p);
        cpa16(uX + off, xs, p);
    }
    if (tid < 8) {
        int o = tid * 4;
        bool p = (sv + o) < VG;
        const float* ms = p ? (Mb + sv + o) : Mb;
        cpa16(uM + o * 4u, ms, p);
    }
}

__global__ __launch_bounds__(128, 2)
void gemm_tobasis_tc(const float* __restrict__ x,
                     const float* __restrict__ mass,
                     const float* __restrict__ evecs) {
    extern __shared__ uint32_t sm[];
    float* sMall = (float*)(sm + 3 * TB_BUFELEMS);       // [3][32]
    const uint32_t uBase = smem_u32(sm);
    const uint32_t uMbase = smem_u32(sMall);

    const int b     = blockIdx.y;
    const int cbase = blockIdx.x * TB_CHUNK;
    const int tid   = threadIdx.x;
    const int lane  = tid & 31;
    const int wid   = tid >> 5;          // 0..3
    const int m0    = (wid & 1) * 64;    // k-eig offset
    const int n0    = (wid >> 1) * 64;   // d offset
    const int g     = lane >> 2;
    const int t     = lane & 3;

    const float* Eb = evecs + (size_t)b * VG * KEIG;
    const float* Xb = x     + (size_t)b * VG * DCH;
    const float* Mb = mass  + (size_t)b * VG;

    float c[4][8][4];
#pragma unroll
    for (int mi = 0; mi < 4; mi++)
#pragma unroll
        for (int ni = 0; ni < 8; ni++)
#pragma unroll
            for (int q = 0; q < 4; q++) c[mi][ni][q] = 0.f;

#pragma unroll
    for (int s = 0; s < 3; s++) {
        tb_issue(cbase + s * TB_ROWS,
                 uBase + (uint32_t)(s * TB_BUFELEMS) * 4u,
                 uBase + (uint32_t)(s * TB_BUFELEMS + TB_ROWS * TB_P) * 4u,
                 uMbase + (uint32_t)(s * 32) * 4u,
                 Eb, Xb, Mb, tid);
        CP_COMMIT();
    }

    int bi = 0;
    for (int s = 0; s < TB_NS; s++) {
        CP_WAIT2();
        __syncthreads();
        const uint32_t* sE = sm + bi * TB_BUFELEMS;
        const uint32_t* sX = sE + TB_ROWS * TB_P;
        const float* sMs = sMall + bi * 32;

#pragma unroll
        for (int kv = 0; kv < TB_ROWS; kv += 8) {
            const uint32_t* eLo = sE + (kv + t) * TB_P;
            const uint32_t* eHi = sE + (kv + t + 4) * TB_P;
            const uint32_t* xLo = sX + (kv + t) * TB_P;
            const uint32_t* xHi = sX + (kv + t + 4) * TB_P;
            float mLo = sMs[kv + t];
            float mHi = sMs[kv + t + 4];
            uint32_t af[4][4], bf[8][2];
#pragma unroll
            for (int mi = 0; mi < 4; mi++) {
                int mIdx = m0 + mi * 16 + g;
                af[mi][0] = f2tf32(__uint_as_float(eLo[mIdx]));
                af[mi][1] = f2tf32(__uint_as_float(eLo[mIdx + 8]));
                af[mi][2] = f2tf32(__uint_as_float(eHi[mIdx]));
                af[mi][3] = f2tf32(__uint_as_float(eHi[mIdx + 8]));
            }
#pragma unroll
            for (int ni = 0; ni < 8; ni++) {
                int nIdx = n0 + ni * 8 + g;
                bf[ni][0] = f2tf32(__uint_as_float(xLo[nIdx]) * mLo);
                bf[ni][1] = f2tf32(__uint_as_float(xHi[nIdx]) * mHi);
            }
#pragma unroll
            for (int mi = 0; mi < 4; mi++)
#pragma unroll
                for (int ni = 0; ni < 8; ni++) mma8(c[mi][ni], af[mi], bf[ni]);
        }
        __syncthreads();
        if (s + 3 < TB_NS) {
            tb_issue(cbase + (s + 3) * TB_ROWS,
                     uBase + (uint32_t)(bi * TB_BUFELEMS) * 4u,
                     uBase + (uint32_t)(bi * TB_BUFELEMS + TB_ROWS * TB_P) * 4u,
                     uMbase + (uint32_t)(bi * 32) * 4u,
                     Eb, Xb, Mb, tid);
        }
        CP_COMMIT();
        if (++bi == 3) bi = 0;
    }

    // epilogue: private partial slab, plain stores
    float* dst = g_part + ((size_t)(b * NCHUNK + blockIdx.x) << 14);
#pragma unroll
    for (int mi = 0; mi < 4; mi++) {
        int r0 = m0 + mi * 16 + g;
#pragma unroll
        for (int ni = 0; ni < 8; ni++) {
            int col = n0 + ni * 8 + 2 * t;
            *(float2*)&dst[r0 * DCH + col] =
                make_float2(c[mi][ni][0], c[mi][ni][1]);
            *(float2*)&dst[(r0 + 8) * DCH + col] =
                make_float2(c[mi][ni][2], c[mi][ni][3]);
        }
    }
}

// ---------------------------------------------------------------------------
// Kernel B: reduce NCHUNK partials + exp scale; store TF32 BITS transposed
// ---------------------------------------------------------------------------
__global__ void spectral_reduce_scale(const float* __restrict__ evals,
                                      const float* __restrict__ tdiff) {
    int i = blockIdx.x * 256 + threadIdx.x;   // over b*K*D
    if (i >= BGR * KEIG * DCH) return;
    int d = i & 127;
    int k = (i >> 7) & 127;
    int b = i >> 14;
    const float* p = g_part + ((size_t)(b * NCHUNK) << 14) + k * DCH + d;
    float s = 0.f;
#pragma unroll
    for (int ch = 0; ch < NCHUNK; ch++) s += p[(size_t)ch << 14];
    float tt = fmaxf(tdiff[d], 1e-8f);
    float val = s * expf(-evals[b * KEIG + k] * tt);
    g_shat_T[(b << 14) + (d << 7) + k] = __uint_as_float(f2tf32(val));
}

// ---------------------------------------------------------------------------
// Kernel C (from_basis): out[v,d] = sum_k E[v,k] * S_T[d,k]
// 128 threads, 2x2 warps of 64x64. 4 k-chunks of 32, 3-stage pipeline.
// S pre-rounded tf32 (no cvt); E cvt at frag read.
// ---------------------------------------------------------------------------
__device__ __forceinline__ void fb_issue(int k0, uint32_t uE, uint32_t uS,
                                         const float* Eb, const float* Sb,
                                         int v0, int tid) {
#pragma unroll
    for (int r = 0; r < 8; r++) {
        int idx = r * 128 + tid;          // 0..1023
        int row = idx >> 3;               // 0..127
        int c4  = idx & 7;                // 0..7
        uint32_t off = (uint32_t)(row * FB_P + c4 * 4) * 4u;
        cpa16(uS + off, Sb + (size_t)row * KEIG + k0 + c4 * 4, true);
        int v = v0 + row;
        bool p = v < VG;
        const float* es = p ? (Eb + (size_t)v * KEIG + k0 + c4 * 4) : Eb;
        cpa16(uE + off, es, p);
    }
}

__global__ __launch_bounds__(128, 2)
void gemm_frombasis_tc(const float* __restrict__ evecs,
                       float* __restrict__ out) {
    extern __shared__ uint32_t sm[];
    const uint32_t uBase = smem_u32(sm);

    const int b    = blockIdx.y;
    const int v0   = blockIdx.x * 128;
    const int tid  = threadIdx.x;
    const int lane = tid & 31;
    const int wid  = tid >> 5;           // 0..3
    const int m0   = (wid & 1) * 64;     // v offset
    const int n0   = (wid >> 1) * 64;    // d offset
    const int g    = lane >> 2;
    const int t    = lane & 3;

    const float* Eb = evecs    + (size_t)b * VG * KEIG;
    const float* Sb = g_shat_T + ((size_t)b << 14);

    float c[4][8][4];
#pragma unroll
    for (int mi = 0; mi < 4; mi++)
#pragma unroll
        for (int ni = 0; ni < 8; ni++)
#pragma unroll
            for (int q = 0; q < 4; q++) c[mi][ni][q] = 0.f;

#pragma unroll
    for (int s = 0; s < 3; s++) {
        fb_issue(s * FB_KC,
                 uBase + (uint32_t)(s * FB_BUFELEMS) * 4u,
                 uBase + (uint32_t)(s * FB_BUFELEMS + 128 * FB_P) * 4u,
                 Eb, Sb, v0, tid);
        CP_COMMIT();
    }

    int bi = 0;
#pragma unroll
    for (int ck = 0; ck < FB_NCK; ck++) {
        CP_WAIT2();
        __syncthreads();
        const uint32_t* sE = sm + bi * FB_BUFELEMS;
        const uint32_t* sS = sE + 128 * FB_P;

#pragma unroll
        for (int ks = 0; ks < FB_KC; ks += 8) {
            uint32_t af[4][4], bf[8][2];
#pragma unroll
            for (int mi = 0; mi < 4; mi++) {
                const uint32_t* p = sE + (m0 + mi * 16 + g) * FB_P + ks + t;
                af[mi][0] = f2tf32(__uint_as_float(p[0]));
                af[mi][1] = f2tf32(__uint_as_float(p[8 * FB_P]));
                af[mi][2] = f2tf32(__uint_as_float(p[4]));
                af[mi][3] = f2tf32(__uint_as_float(p[8 * FB_P + 4]));
            }
#pragma unroll
            for (int ni = 0; ni < 8; ni++) {
                const uint32_t* p = sS + (n0 + ni * 8 + g) * FB_P + ks + t;
                bf[ni][0] = p[0];
                bf[ni][1] = p[4];
            }
#pragma unroll
            for (int mi = 0; mi < 4; mi++)
#pragma unroll
                for (int ni = 0; ni < 8; ni++) mma8(c[mi][ni], af[mi], bf[ni]);
        }
        __syncthreads();
        if (ck + 3 < FB_NCK) {
            fb_issue((ck + 3) * FB_KC,
                     uBase + (uint32_t)(bi * FB_BUFELEMS) * 4u,
                     uBase + (uint32_t)(bi * FB_BUFELEMS + 128 * FB_P) * 4u,
                     Eb, Sb, v0, tid);
        }
        CP_COMMIT();
        if (++bi == 3) bi = 0;
    }

    // epilogue: direct, sector-aligned float2 stores
#pragma unroll
    for (int mi = 0; mi < 4; mi++) {
        int vlo = v0 + m0 + mi * 16 + g;
#pragma unroll
        for (int ni = 0; ni < 8; ni++) {
            int col = n0 + ni * 8 + 2 * t;
            if (vlo < VG)
                *(float2*)(out + (size_t)(b * VG + vlo) * DCH + col) =
                    make_float2(c[mi][ni][0], c[mi][ni][1]);
            if (vlo + 8 < VG)
                *(float2*)(out + (size_t)(b * VG + vlo + 8) * DCH + col) =
                    make_float2(c[mi][ni][2], c[mi][ni][3]);
        }
    }
}

// ---------------------------------------------------------------------------
// Launch
// Inputs: 0:x (V,D) f32, 1:mass (V,) f32, 2:evals (B*K,) f32,
// 3:evecs (V,K) f32, 4:diffusion_time (D,) f32, 5:batch (V,) i32, 6:bs
// Output: (V,D) f32
// ---------------------------------------------------------------------------
extern "C" void kernel_launch(void* const* d_in, const int* in_sizes, int n_in,
                              void* d_out, int out_size) {
    const float* x     = (const float*)d_in[0];
    const float* mass  = (const float*)d_in[1];
    const float* evals = (const float*)d_in[2];
    const float* evecs = (const float*)d_in[3];
    const float* tdiff = (const float*)d_in[4];
    float* out = (float*)d_out;

    (void)in_sizes; (void)n_in; (void)out_size;

    const int TB_SMEM = (3 * TB_BUFELEMS + 3 * 32) * 4;  // 104832 B
    const int FB_SMEM = (3 * FB_BUFELEMS) * 4;           // 110592 B
    cudaFuncSetAttribute(gemm_tobasis_tc,
                         cudaFuncAttributeMaxDynamicSharedMemorySize, TB_SMEM);
    cudaFuncSetAttribute(gemm_frombasis_tc,
                         cudaFuncAttributeMaxDynamicSharedMemorySize, FB_SMEM);

    dim3 gridA(NCHUNK, BGR);
    gemm_tobasis_tc<<<gridA, 128, TB_SMEM>>>(x, mass, evecs);

    spectral_reduce_scale<<<(BGR * KEIG * DCH + 255) / 256, 256>>>(evals, tdiff);

    dim3 gridC((VG + 127) / 128, BGR);
    gemm_frombasis_tc<<<gridC, 128, FB_SMEM>>>(evecs, out);
}